// round 11
// baseline (speedup 1.0000x reference)
#include <cuda_runtime.h>
#include <cstdint>

// ===========================================================================
// MHA B=2,S=2048,E=1024,H=16,D=64 fp32.  SIMT f32x2 everywhere.
//  - GEMMs: R5 engine + launch_bounds(256,2) (measured 562us proj, 190us out).
//  - attention: PAIR-SPLIT flash. 256 thr/CTA; thread t = (row=t>>1, half=t&1).
//    Thread computes scores for its 32-key half of each tile and accumulates
//    only its 32-float D-half of O (o2[16] ull -> 32 regs). Pair exchanges
//    max / lsum / p via shfl.xor(1) (same warp). No end merge. True reg
//    demand ~105 < 128 cap -> 2 CTAs/SM, 16 warps/SM, no spills.
// ===========================================================================

typedef unsigned long long ull;
#define DI __device__ __forceinline__

DI ull pk2(float lo, float hi) {
    ull r; asm("mov.b64 %0, {%1,%2};" : "=l"(r) : "f"(lo), "f"(hi)); return r;
}
DI void upk2(ull v, float& lo, float& hi) {
    asm("mov.b64 {%0,%1}, %2;" : "=f"(lo), "=f"(hi) : "l"(v));
}
DI ull ffma2(ull a, ull b, ull c) {
    ull d; asm("fma.rn.f32x2 %0, %1, %2, %3;" : "=l"(d) : "l"(a), "l"(b), "l"(c)); return d;
}
DI ull fmul2(ull a, ull b) {
    ull d; asm("mul.rn.f32x2 %0, %1, %2;" : "=l"(d) : "l"(a), "l"(b)); return d;
}

constexpr int B = 2, S = 2048, E = 1024, H = 16, D = 64;

__device__ float g_q[B * H * S * D];
__device__ float g_k[B * H * S * D];
__device__ float g_v[B * H * S * D];
__device__ float g_att[B * S * E];

// ---------------------------------------------------------------------------
// R5 GEMM engine with launch_bounds(256,2) (measured best).
// ---------------------------------------------------------------------------
template <int MODE>
DI void gemm_body(const float* __restrict__ X, const float* __restrict__ W,
                  const float* __restrict__ bias, float* __restrict__ out)
{
    __shared__ __align__(16) float As[8][132];
    __shared__ __align__(16) float Ws[8][132];

    const int tid = threadIdx.x;
    const int tx = tid & 15, ty = tid >> 4;
    const int m0 = blockIdx.y * 128;
    const int n0 = blockIdx.x * 128;
    const int lr = tid >> 1;
    const int lc = (tid & 1) << 2;

    const float* Xp = X + (size_t)(m0 + lr) * 1024 + lc;
    const float* Wp = W + (size_t)(n0 + lr) * 1024 + lc;

    ull acc[8][4];
#pragma unroll
    for (int i = 0; i < 8; i++)
#pragma unroll
        for (int j = 0; j < 4; j++) acc[i][j] = 0ull;

    float4 av = *(const float4*)Xp;
    float4 wv = *(const float4*)Wp;

    for (int k0 = 0; k0 < 1024; k0 += 8) {
        __syncthreads();
        As[lc + 0][lr] = av.x; As[lc + 1][lr] = av.y;
        As[lc + 2][lr] = av.z; As[lc + 3][lr] = av.w;
        Ws[lc + 0][lr] = wv.x; Ws[lc + 1][lr] = wv.y;
        Ws[lc + 2][lr] = wv.z; Ws[lc + 3][lr] = wv.w;
        __syncthreads();
        if (k0 + 8 < 1024) {
            av = *(const float4*)(Xp + k0 + 8);
            wv = *(const float4*)(Wp + k0 + 8);
        }
#pragma unroll
        for (int kk = 0; kk < 8; kk++) {
            float4 a0 = *(const float4*)&As[kk][ty * 4];
            float4 a1 = *(const float4*)&As[kk][64 + ty * 4];
            ulonglong2 b0 = *(const ulonglong2*)&Ws[kk][tx * 4];
            ulonglong2 b1 = *(const ulonglong2*)&Ws[kk][64 + tx * 4];
            float a[8] = {a0.x, a0.y, a0.z, a0.w, a1.x, a1.y, a1.z, a1.w};
            ull bv[4] = {b0.x, b0.y, b1.x, b1.y};
#pragma unroll
            for (int i = 0; i < 8; i++) {
                ull a2 = pk2(a[i], a[i]);
#pragma unroll
                for (int j = 0; j < 4; j++) acc[i][j] = ffma2(a2, bv[j], acc[i][j]);
            }
        }
    }

    float4 bias0 = *(const float4*)&bias[n0 + tx * 4];
    float4 bias1 = *(const float4*)&bias[n0 + 64 + tx * 4];

#pragma unroll
    for (int i = 0; i < 8; i++) {
        int m = m0 + (i >> 2) * 64 + ty * 4 + (i & 3);
        float4 r0, r1;
        upk2(acc[i][0], r0.x, r0.y); upk2(acc[i][1], r0.z, r0.w);
        upk2(acc[i][2], r1.x, r1.y); upk2(acc[i][3], r1.z, r1.w);
        r0.x += bias0.x; r0.y += bias0.y; r0.z += bias0.z; r0.w += bias0.w;
        r1.x += bias1.x; r1.y += bias1.y; r1.z += bias1.z; r1.w += bias1.w;
        if (MODE == 0) {
            int bb = m >> 11, ss = m & 2047;
            int nA = n0 + tx * 4;
            int nB = n0 + 64 + tx * 4;
            int hA = nA >> 6, dA = nA & 63;
            int hB = nB >> 6, dB = nB & 63;
            *(float4*)&out[((size_t)(bb * H + hA) * S + ss) * D + dA] = r0;
            *(float4*)&out[((size_t)(bb * H + hB) * S + ss) * D + dB] = r1;
        } else {
            *(float4*)&out[(size_t)m * 1024 + n0 + tx * 4] = r0;
            *(float4*)&out[(size_t)m * 1024 + n0 + 64 + tx * 4] = r1;
        }
    }
}

__global__ __launch_bounds__(256, 2) void gemm_proj(const float* __restrict__ xq,
                                                    const float* __restrict__ xk,
                                                    const float* __restrict__ xv,
                                                    const float* __restrict__ Wq,
                                                    const float* __restrict__ Wk,
                                                    const float* __restrict__ Wv,
                                                    const float* __restrict__ bq,
                                                    const float* __restrict__ bk,
                                                    const float* __restrict__ bv,
                                                    float* __restrict__ oq,
                                                    float* __restrict__ ok,
                                                    float* __restrict__ ov)
{
    const int z = blockIdx.z;
    const float* X = (z == 0) ? xq : (z == 1) ? xk : xv;
    const float* W = (z == 0) ? Wq : (z == 1) ? Wk : Wv;
    const float* bb = (z == 0) ? bq : (z == 1) ? bk : bv;
    float* out = (z == 0) ? oq : (z == 1) ? ok : ov;
    gemm_body<0>(X, W, bb, out);
}

__global__ __launch_bounds__(256, 2) void gemm_out(const float* __restrict__ X,
                                                   const float* __restrict__ W,
                                                   const float* __restrict__ bias,
                                                   float* __restrict__ out)
{
    gemm_body<1>(X, W, bias, out);
}

// ---------------------------------------------------------------------------
// Pair-split flash attention.
// BQ=128 rows/CTA, 256 threads: row = t>>1, half = t&1 (adjacent lanes!).
// Scores: thread covers keys [half*32, half*32+32) of each 64-key tile,
//   in 2 groups of 16 (s2[8]).
// Softmax: pair-common m/l via shfl.xor(1); p exchanged via 8 ull shfls.
// PV: thread accumulates O[row][half*32 .. +32) over all 64 keys (o2[16]).
// Q smem stride 65 (scalar reads); K transposed [d][68]; V [key][64].
// ---------------------------------------------------------------------------
constexpr int BQ = 128, TK = 64;
constexpr int QSTR = 65, KSTR = 68;
constexpr int ATTN_SMEM = (BQ * QSTR + TK * KSTR + TK * D) * 4;  // 67072

__global__ __launch_bounds__(256, 2) void attn_kernel(const float* __restrict__ Q,
                                                      const float* __restrict__ K,
                                                      const float* __restrict__ V,
                                                      float* __restrict__ Oout)
{
    extern __shared__ float sm[];
    float* Qs  = sm;                       // [128][65]
    float* Kst = sm + BQ * QSTR;           // [64 d][68 keys]
    float* Vs  = Kst + TK * KSTR;          // [64 keys][64 d]

    const int t    = threadIdx.x;
    const int row  = t >> 1;
    const int half = t & 1;
    const int bh = blockIdx.y;
    const int q0 = blockIdx.x * BQ;
    const float* Qb = Q + (size_t)bh * (S * D);
    const float* Kb = K + (size_t)bh * (S * D);
    const float* Vb = V + (size_t)bh * (S * D);

    // load Q tile (scaled): 128x64, 256 threads -> 32 elems each
#pragma unroll
    for (int i = 0; i < 32; i++) {
        int idx = i * 256 + t;
        int r = idx >> 6, d = idx & 63;
        Qs[r * QSTR + d] = Qb[(size_t)(q0 + r) * D + d] * 0.125f;
    }

    ull o2[16];
#pragma unroll
    for (int i = 0; i < 16; i++) o2[i] = 0ull;
    float m_run = -3.0e38f, l_run = 0.0f;

    const float* qrow = &Qs[row * QSTR];
    const int kbase = half * 32;           // this thread's 32 keys in the tile
    const int vcol  = half * 32;           // this thread's D-half columns

    for (int kt = 0; kt < S; kt += TK) {
        __syncthreads();
#pragma unroll
        for (int i = 0; i < 16; i++) {
            int idx = i * 256 + t;
            int j = idx >> 6, d = idx & 63;
            Kst[d * KSTR + j] = Kb[(size_t)(kt + j) * D + d];
            Vs[j * D + d]     = Vb[(size_t)(kt + j) * D + d];
        }
        __syncthreads();

#pragma unroll
        for (int gi = 0; gi < 2; gi++) {
            const int g16 = kbase + gi * 16;   // own 16-key group
            ull s2[8];
#pragma unroll
            for (int i = 0; i < 8; i++) s2[i] = 0ull;

#pragma unroll
            for (int dc = 0; dc < D; dc += 16) {
                float qf[16];
#pragma unroll
                for (int u = 0; u < 16; u++) qf[u] = qrow[dc + u];
#pragma unroll
                for (int dd = 0; dd < 16; dd++) {
                    ull q2 = pk2(qf[dd], qf[dd]);
                    const ulonglong2* kr =
                        (const ulonglong2*)&Kst[(dc + dd) * KSTR + g16];
#pragma unroll
                    for (int u = 0; u < 4; u++) {
                        ulonglong2 kv = kr[u];
                        s2[2 * u]     = ffma2(q2, kv.x, s2[2 * u]);
                        s2[2 * u + 1] = ffma2(q2, kv.y, s2[2 * u + 1]);
                    }
                }
            }

            // pair-common online softmax
            float gmax = -3.0e38f;
#pragma unroll
            for (int i = 0; i < 8; i++) {
                float x, y; upk2(s2[i], x, y);
                gmax = fmaxf(gmax, fmaxf(x, y));
            }
            gmax = fmaxf(gmax, __shfl_xor_sync(0xffffffffu, gmax, 1));
            if (__any_sync(0xffffffffu, gmax > m_run)) {
                float mnew = fmaxf(m_run, gmax);
                float alpha = __expf(m_run - mnew);
                l_run *= alpha;
                ull al2 = pk2(alpha, alpha);
#pragma unroll
                for (int i = 0; i < 16; i++) o2[i] = fmul2(o2[i], al2);
                m_run = mnew;
            }
            float lsum = 0.0f;
#pragma unroll
            for (int i = 0; i < 8; i++) {
                float x, y; upk2(s2[i], x, y);
                float p0 = __expf(x - m_run), p1 = __expf(y - m_run);
                lsum += p0 + p1;
                s2[i] = pk2(p0, p1);
            }
            l_run += lsum + __shfl_xor_sync(0xffffffffu, lsum, 1);

            // exchange p with pair partner (its 16 keys at g16 ^ 32)
            ull sp[8];
#pragma unroll
            for (int i = 0; i < 8; i++)
                sp[i] = __shfl_xor_sync(0xffffffffu, s2[i], 1);
            const int pg16 = g16 ^ 32;

            // PV over 32 keys (own 16 + partner 16), D-half columns only
#pragma unroll
            for (int j2 = 0; j2 < 8; j2++) {
                {   // own keys g16 + 2*j2, +1
                    int j = g16 + 2 * j2;
                    float p0, p1; upk2(s2[j2], p0, p1);
                    ull pa = pk2(p0, p0), pb = pk2(p1, p1);
                    const ulonglong2* v0 = (const ulonglong2*)&Vs[j * D + vcol];
                    const ulonglong2* v1 = (const ulonglong2*)&Vs[(j + 1) * D + vcol];
#pragma unroll
                    for (int cp = 0; cp < 8; cp++) {
                        ulonglong2 va = v0[cp];
                        ulonglong2 vb = v1[cp];
                        o2[2 * cp]     = ffma2(pa, va.x, o2[2 * cp]);
                        o2[2 * cp + 1] = ffma2(pa, va.y, o2[2 * cp + 1]);
                        o2[2 * cp]     = ffma2(pb, vb.x, o2[2 * cp]);
                        o2[2 * cp + 1] = ffma2(pb, vb.y, o2[2 * cp + 1]);
                    }
                }
                {   // partner keys pg16 + 2*j2, +1
                    int j = pg16 + 2 * j2;
                    float p0, p1; upk2(sp[j2], p0, p1);
                    ull pa = pk2(p0, p0), pb = pk2(p1, p1);
                    const ulonglong2* v0 = (const ulonglong2*)&Vs[j * D + vcol];
                    const ulonglong2* v1 = (const ulonglong2*)&Vs[(j + 1) * D + vcol];
#pragma unroll
                    for (int cp = 0; cp < 8; cp++) {
                        ulonglong2 va = v0[cp];
                        ulonglong2 vb = v1[cp];
                        o2[2 * cp]     = ffma2(pa, va.x, o2[2 * cp]);
                        o2[2 * cp + 1] = ffma2(pa, va.y, o2[2 * cp + 1]);
                        o2[2 * cp]     = ffma2(pb, vb.x, o2[2 * cp]);
                        o2[2 * cp + 1] = ffma2(pb, vb.y, o2[2 * cp + 1]);
                    }
                }
            }
        }
    }

    // epilogue: each thread writes its own D-half (l is pair-common)
    float inv_l = 1.0f / l_run;
    int bb = bh >> 4, hh = bh & 15;
    float* dst = Oout + (size_t)(bb * S + q0 + row) * E + hh * D + vcol;
#pragma unroll
    for (int cp = 0; cp < 8; cp++) {
        float x0, x1, x2, x3;
        upk2(o2[2 * cp], x0, x1);
        upk2(o2[2 * cp + 1], x2, x3);
        float4 o4 = { x0 * inv_l, x1 * inv_l, x2 * inv_l, x3 * inv_l };
        *(float4*)&dst[cp * 4] = o4;
    }
}

// ---------------------------------------------------------------------------
extern "C" void kernel_launch(void* const* d_in, const int* in_sizes, int n_in,
                              void* d_out, int out_size)
{
    const float* query = (const float*)d_in[0];
    const float* key   = (const float*)d_in[1];
    const float* value = (const float*)d_in[2];
    const float* Wq    = (const float*)d_in[3];
    const float* bq    = (const float*)d_in[4];
    const float* Wk    = (const float*)d_in[5];
    const float* bk    = (const float*)d_in[6];
    const float* Wv    = (const float*)d_in[7];
    const float* bv    = (const float*)d_in[8];
    const float* Wo    = (const float*)d_in[9];
    const float* bo    = (const float*)d_in[10];

    void *pq, *pk, *pv, *patt;
    cudaGetSymbolAddress(&pq, g_q);
    cudaGetSymbolAddress(&pk, g_k);
    cudaGetSymbolAddress(&pv, g_v);
    cudaGetSymbolAddress(&patt, g_att);

    cudaFuncSetAttribute(attn_kernel, cudaFuncAttributeMaxDynamicSharedMemorySize,
                         ATTN_SMEM);

    dim3 pgrid(8, 32, 3);
    gemm_proj<<<pgrid, 256>>>(query, key, value, Wq, Wk, Wv, bq, bk, bv,
                              (float*)pq, (float*)pk, (float*)pv);

    dim3 agrid(S / BQ, B * H);  // (16, 32)
    attn_kernel<<<agrid, 256, ATTN_SMEM>>>((const float*)pq, (const float*)pk,
                                           (const float*)pv, (float*)patt);

    dim3 ggrid(8, 32);
    gemm_out<<<ggrid, 256>>>((const float*)patt, Wo, bo, (float*)d_out);
}

// round 12
// speedup vs baseline: 1.3255x; 1.3255x over previous
#include <cuda_runtime.h>
#include <cstdint>

// ===========================================================================
// MHA B=2,S=2048,E=1024,H=16,D=64 fp32.  SIMT f32x2 everywhere.
//  - GEMMs: R5 engine + launch_bounds(256,2) (measured 562us proj, 190us out).
//  - attention: R5 structure EXACTLY (1 row/thread, BQ=128, group-16 online
//    softmax, scalar stride-65 Q reads, broadcast K/V) + launch_bounds(128,3)
//    (3 CTAs/SM) + float4 K/V tile loads.
//  Pair/key-split and 2-row variants all measured worse (R7-R11) — abandoned.
// ===========================================================================

typedef unsigned long long ull;
#define DI __device__ __forceinline__

DI ull pk2(float lo, float hi) {
    ull r; asm("mov.b64 %0, {%1,%2};" : "=l"(r) : "f"(lo), "f"(hi)); return r;
}
DI void upk2(ull v, float& lo, float& hi) {
    asm("mov.b64 {%0,%1}, %2;" : "=f"(lo), "=f"(hi) : "l"(v));
}
DI ull ffma2(ull a, ull b, ull c) {
    ull d; asm("fma.rn.f32x2 %0, %1, %2, %3;" : "=l"(d) : "l"(a), "l"(b), "l"(c)); return d;
}
DI ull fmul2(ull a, ull b) {
    ull d; asm("mul.rn.f32x2 %0, %1, %2;" : "=l"(d) : "l"(a), "l"(b)); return d;
}

constexpr int B = 2, S = 2048, E = 1024, H = 16, D = 64;

__device__ float g_q[B * H * S * D];
__device__ float g_k[B * H * S * D];
__device__ float g_v[B * H * S * D];
__device__ float g_att[B * S * E];

// ---------------------------------------------------------------------------
// R5 GEMM engine with launch_bounds(256,2) (measured best).
// ---------------------------------------------------------------------------
template <int MODE>
DI void gemm_body(const float* __restrict__ X, const float* __restrict__ W,
                  const float* __restrict__ bias, float* __restrict__ out)
{
    __shared__ __align__(16) float As[8][132];
    __shared__ __align__(16) float Ws[8][132];

    const int tid = threadIdx.x;
    const int tx = tid & 15, ty = tid >> 4;
    const int m0 = blockIdx.y * 128;
    const int n0 = blockIdx.x * 128;
    const int lr = tid >> 1;
    const int lc = (tid & 1) << 2;

    const float* Xp = X + (size_t)(m0 + lr) * 1024 + lc;
    const float* Wp = W + (size_t)(n0 + lr) * 1024 + lc;

    ull acc[8][4];
#pragma unroll
    for (int i = 0; i < 8; i++)
#pragma unroll
        for (int j = 0; j < 4; j++) acc[i][j] = 0ull;

    float4 av = *(const float4*)Xp;
    float4 wv = *(const float4*)Wp;

    for (int k0 = 0; k0 < 1024; k0 += 8) {
        __syncthreads();
        As[lc + 0][lr] = av.x; As[lc + 1][lr] = av.y;
        As[lc + 2][lr] = av.z; As[lc + 3][lr] = av.w;
        Ws[lc + 0][lr] = wv.x; Ws[lc + 1][lr] = wv.y;
        Ws[lc + 2][lr] = wv.z; Ws[lc + 3][lr] = wv.w;
        __syncthreads();
        if (k0 + 8 < 1024) {
            av = *(const float4*)(Xp + k0 + 8);
            wv = *(const float4*)(Wp + k0 + 8);
        }
#pragma unroll
        for (int kk = 0; kk < 8; kk++) {
            float4 a0 = *(const float4*)&As[kk][ty * 4];
            float4 a1 = *(const float4*)&As[kk][64 + ty * 4];
            ulonglong2 b0 = *(const ulonglong2*)&Ws[kk][tx * 4];
            ulonglong2 b1 = *(const ulonglong2*)&Ws[kk][64 + tx * 4];
            float a[8] = {a0.x, a0.y, a0.z, a0.w, a1.x, a1.y, a1.z, a1.w};
            ull bv[4] = {b0.x, b0.y, b1.x, b1.y};
#pragma unroll
            for (int i = 0; i < 8; i++) {
                ull a2 = pk2(a[i], a[i]);
#pragma unroll
                for (int j = 0; j < 4; j++) acc[i][j] = ffma2(a2, bv[j], acc[i][j]);
            }
        }
    }

    float4 bias0 = *(const float4*)&bias[n0 + tx * 4];
    float4 bias1 = *(const float4*)&bias[n0 + 64 + tx * 4];

#pragma unroll
    for (int i = 0; i < 8; i++) {
        int m = m0 + (i >> 2) * 64 + ty * 4 + (i & 3);
        float4 r0, r1;
        upk2(acc[i][0], r0.x, r0.y); upk2(acc[i][1], r0.z, r0.w);
        upk2(acc[i][2], r1.x, r1.y); upk2(acc[i][3], r1.z, r1.w);
        r0.x += bias0.x; r0.y += bias0.y; r0.z += bias0.z; r0.w += bias0.w;
        r1.x += bias1.x; r1.y += bias1.y; r1.z += bias1.z; r1.w += bias1.w;
        if (MODE == 0) {
            int bb = m >> 11, ss = m & 2047;
            int nA = n0 + tx * 4;
            int nB = n0 + 64 + tx * 4;
            int hA = nA >> 6, dA = nA & 63;
            int hB = nB >> 6, dB = nB & 63;
            *(float4*)&out[((size_t)(bb * H + hA) * S + ss) * D + dA] = r0;
            *(float4*)&out[((size_t)(bb * H + hB) * S + ss) * D + dB] = r1;
        } else {
            *(float4*)&out[(size_t)m * 1024 + n0 + tx * 4] = r0;
            *(float4*)&out[(size_t)m * 1024 + n0 + 64 + tx * 4] = r1;
        }
    }
}

__global__ __launch_bounds__(256, 2) void gemm_proj(const float* __restrict__ xq,
                                                    const float* __restrict__ xk,
                                                    const float* __restrict__ xv,
                                                    const float* __restrict__ Wq,
                                                    const float* __restrict__ Wk,
                                                    const float* __restrict__ Wv,
                                                    const float* __restrict__ bq,
                                                    const float* __restrict__ bk,
                                                    const float* __restrict__ bv,
                                                    float* __restrict__ oq,
                                                    float* __restrict__ ok,
                                                    float* __restrict__ ov)
{
    const int z = blockIdx.z;
    const float* X = (z == 0) ? xq : (z == 1) ? xk : xv;
    const float* W = (z == 0) ? Wq : (z == 1) ? Wk : Wv;
    const float* bb = (z == 0) ? bq : (z == 1) ? bk : bv;
    float* out = (z == 0) ? oq : (z == 1) ? ok : ov;
    gemm_body<0>(X, W, bb, out);
}

__global__ __launch_bounds__(256, 2) void gemm_out(const float* __restrict__ X,
                                                   const float* __restrict__ W,
                                                   const float* __restrict__ bias,
                                                   float* __restrict__ out)
{
    gemm_body<1>(X, W, bias, out);
}

// ---------------------------------------------------------------------------
// R5 flash attention + (128,3) occupancy + float4 tile loads.
// BQ=128 rows/CTA, 128 threads, 1 row/thread.
// Q smem stride 65 (scalar reads, conflict-free); K transposed [d][68];
// V row-major [j][64]. Group-wise online softmax (16 keys/group).
// ---------------------------------------------------------------------------
constexpr int BQ = 128, TK = 64;
constexpr int QSTR = 65, KSTR = 68;
constexpr int ATTN_SMEM = (BQ * QSTR + D * KSTR + TK * D) * 4;  // 67072

__global__ __launch_bounds__(128, 3) void attn_kernel(const float* __restrict__ Q,
                                                      const float* __restrict__ K,
                                                      const float* __restrict__ V,
                                                      float* __restrict__ Oout)
{
    extern __shared__ float sm[];
    float* Qs  = sm;                  // [128][65]
    float* Kst = sm + BQ * QSTR;      // [64 d][68 keys]
    float* Vs  = Kst + D * KSTR;      // [64 keys][64 d]

    const int t  = threadIdx.x;
    const int bh = blockIdx.y;
    const int q0 = blockIdx.x * BQ;
    const float* Qb = Q + (size_t)bh * (S * D);
    const float* Kb = K + (size_t)bh * (S * D);
    const float* Vb = V + (size_t)bh * (S * D);

    // load Q tile scaled (float4 LDG, scalar STS to stride-65 rows)
#pragma unroll
    for (int i = 0; i < 16; i++) {
        int idx = i * 128 + t;            // 0..2047 float4s
        int r = idx >> 4, c4 = idx & 15;  // row, float4-col
        float4 v = *(const float4*)&Qb[(size_t)(q0 + r) * D + c4 * 4];
        float* q = &Qs[r * QSTR + c4 * 4];
        q[0] = v.x * 0.125f; q[1] = v.y * 0.125f;
        q[2] = v.z * 0.125f; q[3] = v.w * 0.125f;
    }

    ull o2[32];
#pragma unroll
    for (int i = 0; i < 32; i++) o2[i] = 0ull;
    float m_run = -3.0e38f, l_run = 0.0f;

    const float* qrow = &Qs[t * QSTR];

    for (int kt = 0; kt < S; kt += TK) {
        __syncthreads();
        // K: float4 LDG + scalar STS transpose; V: float4 LDG + STS.128
#pragma unroll
        for (int i = 0; i < 8; i++) {
            int idx = i * 128 + t;            // 0..1023 float4s
            int j = idx >> 4, d4 = idx & 15;
            float4 kv = *(const float4*)&Kb[(size_t)(kt + j) * D + d4 * 4];
            Kst[(d4 * 4 + 0) * KSTR + j] = kv.x;
            Kst[(d4 * 4 + 1) * KSTR + j] = kv.y;
            Kst[(d4 * 4 + 2) * KSTR + j] = kv.z;
            Kst[(d4 * 4 + 3) * KSTR + j] = kv.w;
            float4 vv = *(const float4*)&Vb[(size_t)(kt + j) * D + d4 * 4];
            *(float4*)&Vs[j * D + d4 * 4] = vv;
        }
        __syncthreads();

#pragma unroll
        for (int g = 0; g < 4; g++) {
            ull s2[8];
#pragma unroll
            for (int i = 0; i < 8; i++) s2[i] = 0ull;

#pragma unroll
            for (int dc = 0; dc < D; dc += 16) {
                float qf[16];
#pragma unroll
                for (int u = 0; u < 16; u++) qf[u] = qrow[dc + u];
#pragma unroll
                for (int dd = 0; dd < 16; dd++) {
                    ull q2 = pk2(qf[dd], qf[dd]);
                    const ulonglong2* kr =
                        (const ulonglong2*)&Kst[(dc + dd) * KSTR + g * 16];
#pragma unroll
                    for (int u = 0; u < 4; u++) {
                        ulonglong2 kv = kr[u];
                        s2[2 * u]     = ffma2(q2, kv.x, s2[2 * u]);
                        s2[2 * u + 1] = ffma2(q2, kv.y, s2[2 * u + 1]);
                    }
                }
            }

            float gmax = -3.0e38f;
#pragma unroll
            for (int i = 0; i < 8; i++) {
                float x, y; upk2(s2[i], x, y);
                gmax = fmaxf(gmax, fmaxf(x, y));
            }
            if (__any_sync(0xffffffffu, gmax > m_run)) {
                float mnew = fmaxf(m_run, gmax);
                float alpha = __expf(m_run - mnew);
                l_run *= alpha;
                ull al2 = pk2(alpha, alpha);
#pragma unroll
                for (int i = 0; i < 32; i++) o2[i] = fmul2(o2[i], al2);
                m_run = mnew;
            }
            float lsum = 0.0f;
#pragma unroll
            for (int i = 0; i < 8; i++) {
                float x, y; upk2(s2[i], x, y);
                float p0 = __expf(x - m_run), p1 = __expf(y - m_run);
                lsum += p0 + p1;
                s2[i] = pk2(p0, p1);
            }
            l_run += lsum;

#pragma unroll
            for (int j2 = 0; j2 < 8; j2++) {
                int j = g * 16 + 2 * j2;
                float p0, p1; upk2(s2[j2], p0, p1);
                ull pa = pk2(p0, p0), pb = pk2(p1, p1);
                const ulonglong2* v0 = (const ulonglong2*)&Vs[j * D];
                const ulonglong2* v1 = (const ulonglong2*)&Vs[(j + 1) * D];
#pragma unroll
                for (int cp = 0; cp < 16; cp++) {
                    ulonglong2 va = v0[cp];
                    ulonglong2 vb = v1[cp];
                    o2[2 * cp]     = ffma2(pa, va.x, o2[2 * cp]);
                    o2[2 * cp + 1] = ffma2(pa, va.y, o2[2 * cp + 1]);
                    o2[2 * cp]     = ffma2(pb, vb.x, o2[2 * cp]);
                    o2[2 * cp + 1] = ffma2(pb, vb.y, o2[2 * cp + 1]);
                }
            }
        }
    }

    float inv_l = 1.0f / l_run;
    int bb = bh >> 4, hh = bh & 15;
    float* dst = Oout + (size_t)(bb * S + q0 + t) * E + hh * D;
#pragma unroll
    for (int cp = 0; cp < 16; cp++) {
        float x0, x1, x2, x3;
        upk2(o2[2 * cp], x0, x1);
        upk2(o2[2 * cp + 1], x2, x3);
        float4 o4 = { x0 * inv_l, x1 * inv_l, x2 * inv_l, x3 * inv_l };
        *(float4*)&dst[cp * 4] = o4;
    }
}

// ---------------------------------------------------------------------------
extern "C" void kernel_launch(void* const* d_in, const int* in_sizes, int n_in,
                              void* d_out, int out_size)
{
    const float* query = (const float*)d_in[0];
    const float* key   = (const float*)d_in[1];
    const float* value = (const float*)d_in[2];
    const float* Wq    = (const float*)d_in[3];
    const float* bq    = (const float*)d_in[4];
    const float* Wk    = (const float*)d_in[5];
    const float* bk    = (const float*)d_in[6];
    const float* Wv    = (const float*)d_in[7];
    const float* bv    = (const float*)d_in[8];
    const float* Wo    = (const float*)d_in[9];
    const float* bo    = (const float*)d_in[10];

    void *pq, *pk, *pv, *patt;
    cudaGetSymbolAddress(&pq, g_q);
    cudaGetSymbolAddress(&pk, g_k);
    cudaGetSymbolAddress(&pv, g_v);
    cudaGetSymbolAddress(&patt, g_att);

    cudaFuncSetAttribute(attn_kernel, cudaFuncAttributeMaxDynamicSharedMemorySize,
                         ATTN_SMEM);

    dim3 pgrid(8, 32, 3);
    gemm_proj<<<pgrid, 256>>>(query, key, value, Wq, Wk, Wv, bq, bk, bv,
                              (float*)pq, (float*)pk, (float*)pv);

    dim3 agrid(S / BQ, B * H);  // (16, 32)
    attn_kernel<<<agrid, 128, ATTN_SMEM>>>((const float*)pq, (const float*)pk,
                                           (const float*)pv, (float*)patt);

    dim3 ggrid(8, 32);
    gemm_out<<<ggrid, 256>>>((const float*)patt, Wo, bo, (float*)d_out);
}